// round 4
// baseline (speedup 1.0000x reference)
#include <cuda_runtime.h>
#include <cuda_bf16.h>
#include <cfloat>
#include <stdint.h>

// x [64,256,32,32] f32, codebook [1024,256] f32
#define D_DIM   256
#define HW_DIM  1024
#define NPIX    65536
#define KCODE   1024
#define TOT_ELEMS 16777216
#define MARG    1.5e-2f        // >= 2*worst-case bf16 d2 error (~9e-3)

// Scratch (device globals; allocation-free)
__device__ float  g_cn[KCODE];
__device__ float  g_xn[NPIX];
__device__ int    g_idx[NPIX];
__device__ unsigned short g_cand[(size_t)NPIX * 32];  // 8 slots x 4 lanes
__device__ unsigned char  g_cnt[NPIX * 4];
__device__ double g_partial[512];

// ============================ PTX helpers ============================
__device__ __forceinline__ uint32_t smem_u32(const void* p) {
    uint32_t a;
    asm("{ .reg .u64 t; cvta.to.shared.u64 t, %1; cvt.u32.u64 %0, t; }"
        : "=r"(a) : "l"(p));
    return a;
}
#define LDSM4(r0, r1, r2, r3, addr)                                             \
    asm volatile("ldmatrix.sync.aligned.m8n8.x4.shared.b16 {%0,%1,%2,%3}, [%4];" \
                 : "=r"(r0), "=r"(r1), "=r"(r2), "=r"(r3) : "r"(addr))
#define MMA16816(d, a0, a1, a2, a3, b0, b1)                                     \
    asm volatile("mma.sync.aligned.m16n8k16.row.col.f32.bf16.bf16.f32 "         \
                 "{%0,%1,%2,%3}, {%4,%5,%6,%7}, {%8,%9}, {%0,%1,%2,%3};"        \
                 : "+f"((d)[0]), "+f"((d)[1]), "+f"((d)[2]), "+f"((d)[3])       \
                 : "r"(a0), "r"(a1), "r"(a2), "r"(a3), "r"(b0), "r"(b1))

__device__ __forceinline__ uint32_t pack_bf2(float a, float b) {
    unsigned short lo = __bfloat16_as_ushort(__float2bfloat16_rn(a));
    unsigned short hi = __bfloat16_as_ushort(__float2bfloat16_rn(b));
    return (uint32_t)lo | ((uint32_t)hi << 16);
}

// SMEM layout: A[128][264 bf16] (pitch 528B = 33x16B, ldmatrix conflict-free),
// B double buffer, cnorms.
#define PITCHB    528
#define OFF_A     0
#define OFF_B0    67584
#define OFF_B1    135168
#define OFF_CNS   202752
#define SMEM_TOTAL 206848

// ---------------------------------------------------------------------------
// norms (scalar-sequential order — bit-exact-validated in round 2)
// ---------------------------------------------------------------------------
__global__ void cnorm_kernel(const float* __restrict__ cb) {
    int k = blockIdx.x * 256 + threadIdx.x;
    const float* row = cb + (size_t)k * D_DIM;
    float s = 0.f;
    for (int d = 0; d < D_DIM; d++) s = __fadd_rn(s, __fmul_rn(row[d], row[d]));
    g_cn[k] = s;
}
__global__ void xnorm_kernel(const float* __restrict__ x) {
    int b = blockIdx.x, t = threadIdx.x;
    const float* xb = x + (size_t)b * D_DIM * HW_DIM + t * 4;
    float sa[4] = {0.f, 0.f, 0.f, 0.f};
    for (int d = 0; d < D_DIM; d++) {
        float4 v = *(const float4*)(xb + (size_t)d * HW_DIM);
        sa[0] = __fadd_rn(sa[0], __fmul_rn(v.x, v.x));
        sa[1] = __fadd_rn(sa[1], __fmul_rn(v.y, v.y));
        sa[2] = __fadd_rn(sa[2], __fmul_rn(v.z, v.z));
        sa[3] = __fadd_rn(sa[3], __fmul_rn(v.w, v.w));
    }
    int p = b * HW_DIM + t * 4;
#pragma unroll
    for (int j = 0; j < 4; j++) g_xn[p + j] = sa[j];
}

// ---------------------------------------------------------------------------
// candidate push
// ---------------------------------------------------------------------------
__device__ __forceinline__ void consider(float d2, int code, float& rm,
                                         float* cv, unsigned short* ci,
                                         int& cnt, bool& ovf) {
    if (d2 < rm) rm = d2;
    if (d2 <= rm + MARG) {
        if (cnt < 16) { cv[cnt] = d2; ci[cnt] = (unsigned short)code; cnt++; }
        else ovf = true;
    }
}

// ---------------------------------------------------------------------------
// Filter: bf16 HMMA (mma.sync m16n8k16) over all 1024 codes per 128-pixel CTA.
// Collect codes provably able to be (or tie) the exact argmin.
// ---------------------------------------------------------------------------
__global__ __launch_bounds__(256, 1)
void filter_kernel(const float* __restrict__ x, const float* __restrict__ cb) {
    extern __shared__ char smem[];
    uint32_t sbase = smem_u32(smem);
    const int tid = threadIdx.x, wid = tid >> 5, lane = tid & 31;

    float* cns = (float*)(smem + OFF_CNS);
#pragma unroll
    for (int i = 0; i < 4; i++) cns[tid + i * 256] = g_cn[tid + i * 256];

    const int p0 = blockIdx.x * 128, bimg = p0 >> 10, hwb = p0 & 1023;
    const int rc = tid & 127, h = tid >> 7;

    // A tile: x[d][pixel] -> bf16 [pixel][d], pitch 528B
    {
        const float* base = x + ((size_t)bimg * D_DIM + h * 128) * HW_DIM + hwb + rc;
#pragma unroll 4
        for (int i = 0; i < 32; i++) {
            float f0 = base[(size_t)(i * 4 + 0) * HW_DIM];
            float f1 = base[(size_t)(i * 4 + 1) * HW_DIM];
            float f2 = base[(size_t)(i * 4 + 2) * HW_DIM];
            float f3 = base[(size_t)(i * 4 + 3) * HW_DIM];
            uint2 u; u.x = pack_bf2(f0, f1); u.y = pack_bf2(f2, f3);
            *(uint2*)(smem + OFF_A + rc * PITCHB + (h * 128 + i * 4) * 2) = u;
        }
    }
    // B chunk 0
    {
        const float4* src = (const float4*)(cb + (size_t)rc * D_DIM + h * 128);
#pragma unroll 4
        for (int i = 0; i < 32; i++) {
            float4 v = src[i];
            uint2 u; u.x = pack_bf2(v.x, v.y); u.y = pack_bf2(v.z, v.w);
            *(uint2*)(smem + OFF_B0 + rc * PITCHB + (h * 128 + i * 4) * 2) = u;
        }
    }

    // ldmatrix per-lane address pieces
    const int g = lane >> 2, tig = lane & 3;
    const int q = lane >> 3, ro = lane & 7;
    const uint32_t aL = sbase + OFF_A
        + (uint32_t)(wid * 16 + ro + (q & 1) * 8) * PITCHB
        + (uint32_t)((q >> 1) * 8) * 2;
    const uint32_t bL = (uint32_t)(((q >> 1) * 8 + ro) * PITCHB)
        + (uint32_t)((q & 1) * 16);

    const float xnA = g_xn[p0 + wid * 16 + g];
    const float xnB = g_xn[p0 + wid * 16 + g + 8];
    float rmA = FLT_MAX, rmB = FLT_MAX;
    float cvA[16], cvB[16];
    unsigned short ciA[16], ciB[16];
    int cntA = 0, cntB = 0;
    bool ovfA = false, ovfB = false;

    for (int nc = 0; nc < 8; nc++) {
        __syncthreads();   // B[cur] fully written; B[next] free to overwrite
        const uint32_t bbuf  = sbase + ((nc & 1) ? OFF_B1 : OFF_B0);
        const uint32_t bnoff = (nc & 1) ? OFF_B0 : OFF_B1;

        float acc[16][4];
#pragma unroll
        for (int f = 0; f < 16; f++)
#pragma unroll
            for (int r = 0; r < 4; r++) acc[f][r] = 0.f;

#pragma unroll 4
        for (int s = 0; s < 16; s++) {
            uint32_t a0, a1, a2, a3;
            LDSM4(a0, a1, a2, a3, aL + s * 32);

            if (nc < 7) {  // register prefetch of next B chunk -> other buffer
                const float* src = cb + (size_t)((nc + 1) * 128 + rc) * D_DIM
                                      + h * 128 + s * 8;
                float4 v0 = *(const float4*)src;
                float4 v1 = *(const float4*)(src + 4);
                uint4 u;
                u.x = pack_bf2(v0.x, v0.y); u.y = pack_bf2(v0.z, v0.w);
                u.z = pack_bf2(v1.x, v1.y); u.w = pack_bf2(v1.z, v1.w);
                *(uint4*)(smem + bnoff + rc * PITCHB + (h * 128 + s * 8) * 2) = u;
            }

#pragma unroll
            for (int j = 0; j < 8; j++) {
                uint32_t b0, b1, b2, b3;
                LDSM4(b0, b1, b2, b3, bbuf + bL + j * (16 * PITCHB) + s * 32);
                MMA16816(acc[2 * j],     a0, a1, a2, a3, b0, b1);
                MMA16816(acc[2 * j + 1], a0, a1, a2, a3, b2, b3);
            }
        }

        // epilogue: d2 = fl(fl(xn - 2*dot) + cn), running min + candidates
#pragma unroll
        for (int f = 0; f < 16; f++) {
            const int c0 = nc * 128 + f * 8 + tig * 2;
            const float cn0 = cns[c0], cn1 = cns[c0 + 1];
            float dA0 = __fadd_rn(__fadd_rn(xnA, __fmul_rn(-2.f, acc[f][0])), cn0);
            float dA1 = __fadd_rn(__fadd_rn(xnA, __fmul_rn(-2.f, acc[f][1])), cn1);
            float dB0 = __fadd_rn(__fadd_rn(xnB, __fmul_rn(-2.f, acc[f][2])), cn0);
            float dB1 = __fadd_rn(__fadd_rn(xnB, __fmul_rn(-2.f, acc[f][3])), cn1);
            consider(dA0, c0,     rmA, cvA, ciA, cntA, ovfA);
            consider(dA1, c0 + 1, rmA, cvA, ciA, cntA, ovfA);
            consider(dB0, c0,     rmB, cvB, ciB, cntB, ovfB);
            consider(dB1, c0 + 1, rmB, cvB, ciB, cntB, ovfB);
        }
        // share running min across the 4 lanes serving each pixel row
        rmA = fminf(rmA, __shfl_xor_sync(0xffffffffu, rmA, 1));
        rmA = fminf(rmA, __shfl_xor_sync(0xffffffffu, rmA, 2));
        rmB = fminf(rmB, __shfl_xor_sync(0xffffffffu, rmB, 1));
        rmB = fminf(rmB, __shfl_xor_sync(0xffffffffu, rmB, 2));
    }

    // final refilter + write candidates
    {
        const int pA = p0 + wid * 16 + g;
        int kept = 0;
        for (int i = 0; i < cntA; i++)
            if (cvA[i] <= rmA + MARG) {
                if (kept < 8) g_cand[(size_t)pA * 32 + tig * 8 + kept] = ciA[i];
                kept++;
            }
        g_cnt[pA * 4 + tig] = (ovfA || kept > 8) ? (unsigned char)255
                                                 : (unsigned char)kept;
        const int pB = pA + 8;
        kept = 0;
        for (int i = 0; i < cntB; i++)
            if (cvB[i] <= rmB + MARG) {
                if (kept < 8) g_cand[(size_t)pB * 32 + tig * 8 + kept] = ciB[i];
                kept++;
            }
        g_cnt[pB * 4 + tig] = (ovfB || kept > 8) ? (unsigned char)255
                                                 : (unsigned char)kept;
    }
}

// ---------------------------------------------------------------------------
// Rescore: exact fp32 chain (single accumulator, d ascending, fused FMA),
// reference rounding, lowest-index ties. Fallback = full scan.
// ---------------------------------------------------------------------------
__device__ __forceinline__ void eval_code(const float* __restrict__ xp,
                                          const float* __restrict__ cb,
                                          float xn, int k, float& bv, int& bi) {
    const float* ck = cb + (size_t)k * D_DIM;
    float acc = 0.f;
#pragma unroll 8
    for (int d = 0; d < D_DIM; d++)
        acc = __fmaf_rn(xp[(size_t)d * HW_DIM], ck[d], acc);
    float v = __fadd_rn(__fadd_rn(xn, __fmul_rn(-2.f, acc)), g_cn[k]);
    if (v < bv || (v == bv && k < bi)) { bv = v; bi = k; }
}

__global__ void rescore_kernel(const float* __restrict__ x,
                               const float* __restrict__ cb) {
    int p = blockIdx.x * 256 + threadIdx.x;
    int bimg = p >> 10, hw = p & 1023;
    const float* xp = x + (size_t)bimg * D_DIM * HW_DIM + hw;
    float xn = g_xn[p];
    int c[4];
    bool full = false;
#pragma unroll
    for (int t = 0; t < 4; t++) {
        c[t] = g_cnt[p * 4 + t];
        if (c[t] == 255) full = true;
    }
    float bv = FLT_MAX; int bi = 0x7fffffff;
    if (full) {
        for (int k = 0; k < KCODE; k++) eval_code(xp, cb, xn, k, bv, bi);
    } else {
#pragma unroll
        for (int t = 0; t < 4; t++)
            for (int i = 0; i < c[t]; i++)
                eval_code(xp, cb, xn, g_cand[(size_t)p * 32 + t * 8 + i], bv, bi);
    }
    g_idx[p] = bi;
}

// ---------------------------------------------------------------------------
// Output: gather + STE rounding + loss partial
// ---------------------------------------------------------------------------
__global__ __launch_bounds__(256)
void output_kernel(const float* __restrict__ x, const float* __restrict__ cb,
                   float* __restrict__ out) {
    __shared__ int besti[128];
    __shared__ double red[256];
    const int t = threadIdx.x;
    const int p0 = blockIdx.x * 128, bimg = p0 >> 10, hwb = p0 & 1023;
    if (t < 128) besti[t] = g_idx[p0 + t];
    __syncthreads();

    double lsum = 0.0;
#pragma unroll 4
    for (int m = 0; m < 32; m++) {
        int e4 = m * 256 + t;        // float4 index over 128px x 256d tile
        int d  = e4 >> 5;
        int pp = (e4 & 31) * 4;
        size_t addr = (size_t)(bimg * D_DIM + d) * HW_DIM + hwb + pp;
        float4 xv = *(const float4*)(x + addr);
        float q0 = cb[(size_t)besti[pp + 0] * D_DIM + d];
        float q1 = cb[(size_t)besti[pp + 1] * D_DIM + d];
        float q2 = cb[(size_t)besti[pp + 2] * D_DIM + d];
        float q3 = cb[(size_t)besti[pp + 3] * D_DIM + d];
        float4 o;
        o.x = __fadd_rn(xv.x, __fsub_rn(q0, xv.x));
        o.y = __fadd_rn(xv.y, __fsub_rn(q1, xv.y));
        o.z = __fadd_rn(xv.z, __fsub_rn(q2, xv.z));
        o.w = __fadd_rn(xv.w, __fsub_rn(q3, xv.w));
        *(float4*)(out + addr) = o;
        float d0 = __fsub_rn(xv.x, q0), d1 = __fsub_rn(xv.y, q1);
        float d2 = __fsub_rn(xv.z, q2), d3 = __fsub_rn(xv.w, q3);
        lsum += (double)__fmul_rn(d0, d0) + (double)__fmul_rn(d1, d1)
              + (double)__fmul_rn(d2, d2) + (double)__fmul_rn(d3, d3);
    }
    red[t] = lsum;
    __syncthreads();
    for (int s = 128; s > 0; s >>= 1) {
        if (t < s) red[t] += red[t + s];
        __syncthreads();
    }
    if (t == 0) g_partial[blockIdx.x] = red[0];
}

__global__ void finalize_kernel(float* __restrict__ out, int out_size) {
    __shared__ double red[512];
    int t = threadIdx.x;
    red[t] = g_partial[t];
    __syncthreads();
    for (int s = 256; s > 0; s >>= 1) {
        if (t < s) red[t] += red[t + s];
        __syncthreads();
    }
    if (t == 0) {
        float loss = (float)(1.25 * red[0] / (double)TOT_ELEMS);
        for (int i = TOT_ELEMS; i < out_size; i++) out[i] = loss;
    }
}

// ---------------------------------------------------------------------------
extern "C" void kernel_launch(void* const* d_in, const int* in_sizes, int n_in,
                              void* d_out, int out_size) {
    const float* x  = (const float*)d_in[0];
    const float* cb = (const float*)d_in[1];
    float* out = (float*)d_out;

    cudaFuncSetAttribute(filter_kernel,
                         cudaFuncAttributeMaxDynamicSharedMemorySize, SMEM_TOTAL);

    cnorm_kernel<<<KCODE / 256, 256>>>(cb);
    xnorm_kernel<<<64, 256>>>(x);
    filter_kernel<<<NPIX / 128, 256, SMEM_TOTAL>>>(x, cb);
    rescore_kernel<<<NPIX / 256, 256>>>(x, cb);
    output_kernel<<<NPIX / 128, 256>>>(x, cb, out);
    finalize_kernel<<<1, 512>>>(out, out_size);
}

// round 5
// speedup vs baseline: 1.0111x; 1.0111x over previous
#include <cuda_runtime.h>
#include <cuda_bf16.h>
#include <cfloat>
#include <stdint.h>

// x [64,256,32,32] f32, codebook [1024,256] f32
#define D_DIM   256
#define HW_DIM  1024
#define NPIX    65536
#define KCODE   1024
#define TOT_ELEMS 16777216
#define MARG    1.5e-2f   // >= 2*(bf16 MMA err + bf16 store err), provably safe

// Scratch (device globals; allocation-free)
__device__ float  g_cn[KCODE];
__device__ float  g_xn[NPIX];
__device__ int    g_idx[NPIX];
__device__ unsigned short g_s[(size_t)NPIX * KCODE];   // bf16(cn - 2*dot), 128MB
__device__ unsigned short g_cand[(size_t)NPIX * 32];
__device__ unsigned char  g_cnt[NPIX];
__device__ double g_partial[512];

// ============================ PTX helpers ============================
__device__ __forceinline__ uint32_t smem_u32(const void* p) {
    uint32_t a;
    asm("{ .reg .u64 t; cvta.to.shared.u64 t, %1; cvt.u32.u64 %0, t; }"
        : "=r"(a) : "l"(p));
    return a;
}
#define LDSM4(r0, r1, r2, r3, addr)                                             \
    asm volatile("ldmatrix.sync.aligned.m8n8.x4.shared.b16 {%0,%1,%2,%3}, [%4];" \
                 : "=r"(r0), "=r"(r1), "=r"(r2), "=r"(r3) : "r"(addr))
#define MMA16816(d, a0, a1, a2, a3, b0, b1)                                     \
    asm volatile("mma.sync.aligned.m16n8k16.row.col.f32.bf16.bf16.f32 "         \
                 "{%0,%1,%2,%3}, {%4,%5,%6,%7}, {%8,%9}, {%0,%1,%2,%3};"        \
                 : "+f"((d)[0]), "+f"((d)[1]), "+f"((d)[2]), "+f"((d)[3])       \
                 : "r"(a0), "r"(a1), "r"(a2), "r"(a3), "r"(b0), "r"(b1))

__device__ __forceinline__ uint32_t pack_bf2(float a, float b) {
    unsigned short lo = __bfloat16_as_ushort(__float2bfloat16_rn(a));
    unsigned short hi = __bfloat16_as_ushort(__float2bfloat16_rn(b));
    return (uint32_t)lo | ((uint32_t)hi << 16);
}
__device__ __forceinline__ float bflo(uint32_t u) { return __uint_as_float(u << 16); }
__device__ __forceinline__ float bfhi(uint32_t u) { return __uint_as_float(u & 0xffff0000u); }

// SMEM layout: A[128][264 bf16] (pitch 528B, ldmatrix conflict-free),
// B double buffer, cnorms.
#define PITCHB    528
#define OFF_A     0
#define OFF_B0    67584
#define OFF_B1    135168
#define OFF_CNS   202752
#define SMEM_TOTAL 206848

// ---------------------------------------------------------------------------
// norms (scalar-sequential order — bit-exact-validated in round 2)
// ---------------------------------------------------------------------------
__global__ void cnorm_kernel(const float* __restrict__ cb) {
    int k = blockIdx.x * 256 + threadIdx.x;
    const float* row = cb + (size_t)k * D_DIM;
    float s = 0.f;
    for (int d = 0; d < D_DIM; d++) s = __fadd_rn(s, __fmul_rn(row[d], row[d]));
    g_cn[k] = s;
}
__global__ void xnorm_kernel(const float* __restrict__ x) {
    int b = blockIdx.x, t = threadIdx.x;
    const float* xb = x + (size_t)b * D_DIM * HW_DIM + t * 4;
    float sa[4] = {0.f, 0.f, 0.f, 0.f};
    for (int d = 0; d < D_DIM; d++) {
        float4 v = *(const float4*)(xb + (size_t)d * HW_DIM);
        sa[0] = __fadd_rn(sa[0], __fmul_rn(v.x, v.x));
        sa[1] = __fadd_rn(sa[1], __fmul_rn(v.y, v.y));
        sa[2] = __fadd_rn(sa[2], __fmul_rn(v.z, v.z));
        sa[3] = __fadd_rn(sa[3], __fmul_rn(v.w, v.w));
    }
    int p = b * HW_DIM + t * 4;
#pragma unroll
    for (int j = 0; j < 4; j++) g_xn[p + j] = sa[j];
}

// ---------------------------------------------------------------------------
// Filter GEMM: bf16 HMMA over all 1024 codes per 128-pixel CTA; epilogue
// writes s = fl(cn - 2*dot) as bf16 pairs to g_s. Register-only epilogue.
// ---------------------------------------------------------------------------
__global__ __launch_bounds__(256, 1)
void filter_kernel(const float* __restrict__ x, const float* __restrict__ cb) {
    extern __shared__ char smem[];
    uint32_t sbase = smem_u32(smem);
    const int tid = threadIdx.x, wid = tid >> 5, lane = tid & 31;

    float* cns = (float*)(smem + OFF_CNS);
#pragma unroll
    for (int i = 0; i < 4; i++) cns[tid + i * 256] = g_cn[tid + i * 256];

    const int p0 = blockIdx.x * 128, bimg = p0 >> 10, hwb = p0 & 1023;
    const int rc = tid & 127, h = tid >> 7;

    // A tile: x[d][pixel] -> bf16 [pixel][d], pitch 528B
    {
        const float* base = x + ((size_t)bimg * D_DIM + h * 128) * HW_DIM + hwb + rc;
#pragma unroll 4
        for (int i = 0; i < 32; i++) {
            float f0 = base[(size_t)(i * 4 + 0) * HW_DIM];
            float f1 = base[(size_t)(i * 4 + 1) * HW_DIM];
            float f2 = base[(size_t)(i * 4 + 2) * HW_DIM];
            float f3 = base[(size_t)(i * 4 + 3) * HW_DIM];
            uint2 u; u.x = pack_bf2(f0, f1); u.y = pack_bf2(f2, f3);
            *(uint2*)(smem + OFF_A + rc * PITCHB + (h * 128 + i * 4) * 2) = u;
        }
    }
    // B chunk 0
    {
        const float4* src = (const float4*)(cb + (size_t)rc * D_DIM + h * 128);
#pragma unroll 4
        for (int i = 0; i < 32; i++) {
            float4 v = src[i];
            uint2 u; u.x = pack_bf2(v.x, v.y); u.y = pack_bf2(v.z, v.w);
            *(uint2*)(smem + OFF_B0 + rc * PITCHB + (h * 128 + i * 4) * 2) = u;
        }
    }

    // ldmatrix per-lane address pieces
    const int g = lane >> 2, tig = lane & 3;
    const int q = lane >> 3, ro = lane & 7;
    const uint32_t aL = sbase + OFF_A
        + (uint32_t)(wid * 16 + ro + (q & 1) * 8) * PITCHB
        + (uint32_t)((q >> 1) * 8) * 2;
    const uint32_t bL = (uint32_t)(((q >> 1) * 8 + ro) * PITCHB)
        + (uint32_t)((q & 1) * 16);

    const int rowA = p0 + wid * 16 + g;       // this lane's pixel rows
    const int rowB = rowA + 8;
    unsigned short* sA = g_s + (size_t)rowA * KCODE;
    unsigned short* sB = g_s + (size_t)rowB * KCODE;

    for (int nc = 0; nc < 8; nc++) {
        __syncthreads();   // B[cur] fully written; B[next] free to overwrite
        const uint32_t bbuf  = sbase + ((nc & 1) ? OFF_B1 : OFF_B0);
        const uint32_t bnoff = (nc & 1) ? OFF_B0 : OFF_B1;

        float acc[16][4];
#pragma unroll
        for (int f = 0; f < 16; f++)
#pragma unroll
            for (int r = 0; r < 4; r++) acc[f][r] = 0.f;

#pragma unroll 4
        for (int s = 0; s < 16; s++) {
            uint32_t a0, a1, a2, a3;
            LDSM4(a0, a1, a2, a3, aL + s * 32);

            if (nc < 7) {  // register prefetch of next B chunk -> other buffer
                const float* src = cb + (size_t)((nc + 1) * 128 + rc) * D_DIM
                                      + h * 128 + s * 8;
                float4 v0 = *(const float4*)src;
                float4 v1 = *(const float4*)(src + 4);
                uint4 u;
                u.x = pack_bf2(v0.x, v0.y); u.y = pack_bf2(v0.z, v0.w);
                u.z = pack_bf2(v1.x, v1.y); u.w = pack_bf2(v1.z, v1.w);
                *(uint4*)(smem + bnoff + rc * PITCHB + (h * 128 + s * 8) * 2) = u;
            }

#pragma unroll
            for (int j = 0; j < 8; j++) {
                uint32_t b0, b1, b2, b3;
                LDSM4(b0, b1, b2, b3, bbuf + bL + j * (16 * PITCHB) + s * 32);
                MMA16816(acc[2 * j],     a0, a1, a2, a3, b0, b1);
                MMA16816(acc[2 * j + 1], a0, a1, a2, a3, b2, b3);
            }
        }

        // epilogue: s = fl(cn - 2*dot) -> bf16x2 -> g_s (no local arrays)
#pragma unroll
        for (int f = 0; f < 16; f++) {
            const int c0 = nc * 128 + f * 8 + tig * 2;
            const float cn0 = cns[c0], cn1 = cns[c0 + 1];
            float s0 = __fadd_rn(cn0, __fmul_rn(-2.f, acc[f][0]));
            float s1 = __fadd_rn(cn1, __fmul_rn(-2.f, acc[f][1]));
            float s2 = __fadd_rn(cn0, __fmul_rn(-2.f, acc[f][2]));
            float s3 = __fadd_rn(cn1, __fmul_rn(-2.f, acc[f][3]));
            *(uint32_t*)(sA + c0) = pack_bf2(s0, s1);
            *(uint32_t*)(sB + c0) = pack_bf2(s2, s3);
        }
    }
}

// ---------------------------------------------------------------------------
// Scan: one warp per pixel. Coalesced read of the 1024 bf16 s-values,
// warp min-reduce, collect codes with s <= min + MARG via shfl prefix.
// ---------------------------------------------------------------------------
__global__ __launch_bounds__(256)
void scan_kernel() {
    const int p = blockIdx.x * 8 + (threadIdx.x >> 5);
    const int lane = threadIdx.x & 31;
    const uint4* row = (const uint4*)(g_s + (size_t)p * KCODE);

    uint4 v[4];
#pragma unroll
    for (int i = 0; i < 4; i++) v[i] = row[lane + 32 * i];   // 8 codes per uint4

    float mn = FLT_MAX;
#pragma unroll
    for (int i = 0; i < 4; i++) {
        uint32_t w[4] = {v[i].x, v[i].y, v[i].z, v[i].w};
#pragma unroll
        for (int j = 0; j < 4; j++) {
            mn = fminf(mn, bflo(w[j]));
            mn = fminf(mn, bfhi(w[j]));
        }
    }
#pragma unroll
    for (int off = 16; off > 0; off >>= 1)
        mn = fminf(mn, __shfl_xor_sync(0xffffffffu, mn, off));
    const float thr = mn + MARG;

    // count survivors per lane
    int cnt = 0;
#pragma unroll
    for (int i = 0; i < 4; i++) {
        uint32_t w[4] = {v[i].x, v[i].y, v[i].z, v[i].w};
#pragma unroll
        for (int j = 0; j < 4; j++) {
            if (bflo(w[j]) <= thr) cnt++;
            if (bfhi(w[j]) <= thr) cnt++;
        }
    }
    // exclusive prefix over lanes
    int inc = cnt;
#pragma unroll
    for (int d = 1; d < 32; d <<= 1) {
        int t = __shfl_up_sync(0xffffffffu, inc, d);
        if (lane >= d) inc += t;
    }
    const int base  = inc - cnt;
    const int total = __shfl_sync(0xffffffffu, inc, 31);

    if (total > 32) {
        if (lane == 0) g_cnt[p] = 255;
        return;
    }
    int slot = base;
#pragma unroll
    for (int i = 0; i < 4; i++) {
        uint32_t w[4] = {v[i].x, v[i].y, v[i].z, v[i].w};
        const int cb0 = (lane + 32 * i) * 8;
#pragma unroll
        for (int j = 0; j < 4; j++) {
            if (bflo(w[j]) <= thr)
                g_cand[(size_t)p * 32 + slot++] = (unsigned short)(cb0 + j * 2);
            if (bfhi(w[j]) <= thr)
                g_cand[(size_t)p * 32 + slot++] = (unsigned short)(cb0 + j * 2 + 1);
        }
    }
    if (lane == 0) g_cnt[p] = (unsigned char)total;
}

// ---------------------------------------------------------------------------
// Rescore: exact fp32 chain (single accumulator, d ascending, fused FMA),
// reference rounding, lowest-index ties. Fallback = full scan.
// ---------------------------------------------------------------------------
__device__ __forceinline__ void eval_code(const float* __restrict__ xp,
                                          const float* __restrict__ cb,
                                          float xn, int k, float& bv, int& bi) {
    const float* ck = cb + (size_t)k * D_DIM;
    float acc = 0.f;
#pragma unroll 8
    for (int d = 0; d < D_DIM; d++)
        acc = __fmaf_rn(xp[(size_t)d * HW_DIM], ck[d], acc);
    float v = __fadd_rn(__fadd_rn(xn, __fmul_rn(-2.f, acc)), g_cn[k]);
    if (v < bv || (v == bv && k < bi)) { bv = v; bi = k; }
}

__global__ void rescore_kernel(const float* __restrict__ x,
                               const float* __restrict__ cb) {
    int p = blockIdx.x * 256 + threadIdx.x;
    int bimg = p >> 10, hw = p & 1023;
    const float* xp = x + (size_t)bimg * D_DIM * HW_DIM + hw;
    float xn = g_xn[p];
    int c = g_cnt[p];
    float bv = FLT_MAX; int bi = 0x7fffffff;
    if (c == 255) {
        for (int k = 0; k < KCODE; k++) eval_code(xp, cb, xn, k, bv, bi);
    } else {
        for (int i = 0; i < c; i++)
            eval_code(xp, cb, xn, g_cand[(size_t)p * 32 + i], bv, bi);
    }
    g_idx[p] = bi;
}

// ---------------------------------------------------------------------------
// Output: gather + STE rounding + loss partial
// ---------------------------------------------------------------------------
__global__ __launch_bounds__(256)
void output_kernel(const float* __restrict__ x, const float* __restrict__ cb,
                   float* __restrict__ out) {
    __shared__ int besti[128];
    __shared__ double red[256];
    const int t = threadIdx.x;
    const int p0 = blockIdx.x * 128, bimg = p0 >> 10, hwb = p0 & 1023;
    if (t < 128) besti[t] = g_idx[p0 + t];
    __syncthreads();

    double lsum = 0.0;
#pragma unroll 4
    for (int m = 0; m < 32; m++) {
        int e4 = m * 256 + t;        // float4 index over 128px x 256d tile
        int d  = e4 >> 5;
        int pp = (e4 & 31) * 4;
        size_t addr = (size_t)(bimg * D_DIM + d) * HW_DIM + hwb + pp;
        float4 xv = *(const float4*)(x + addr);
        float q0 = cb[(size_t)besti[pp + 0] * D_DIM + d];
        float q1 = cb[(size_t)besti[pp + 1] * D_DIM + d];
        float q2 = cb[(size_t)besti[pp + 2] * D_DIM + d];
        float q3 = cb[(size_t)besti[pp + 3] * D_DIM + d];
        float4 o;
        o.x = __fadd_rn(xv.x, __fsub_rn(q0, xv.x));
        o.y = __fadd_rn(xv.y, __fsub_rn(q1, xv.y));
        o.z = __fadd_rn(xv.z, __fsub_rn(q2, xv.z));
        o.w = __fadd_rn(xv.w, __fsub_rn(q3, xv.w));
        *(float4*)(out + addr) = o;
        float d0 = __fsub_rn(xv.x, q0), d1 = __fsub_rn(xv.y, q1);
        float d2 = __fsub_rn(xv.z, q2), d3 = __fsub_rn(xv.w, q3);
        lsum += (double)__fmul_rn(d0, d0) + (double)__fmul_rn(d1, d1)
              + (double)__fmul_rn(d2, d2) + (double)__fmul_rn(d3, d3);
    }
    red[t] = lsum;
    __syncthreads();
    for (int s = 128; s > 0; s >>= 1) {
        if (t < s) red[t] += red[t + s];
        __syncthreads();
    }
    if (t == 0) g_partial[blockIdx.x] = red[0];
}

__global__ void finalize_kernel(float* __restrict__ out, int out_size) {
    __shared__ double red[512];
    int t = threadIdx.x;
    red[t] = g_partial[t];
    __syncthreads();
    for (int s = 256; s > 0; s >>= 1) {
        if (t < s) red[t] += red[t + s];
        __syncthreads();
    }
    if (t == 0) {
        float loss = (float)(1.25 * red[0] / (double)TOT_ELEMS);
        for (int i = TOT_ELEMS; i < out_size; i++) out[i] = loss;
    }
}

// ---------------------------------------------------------------------------
extern "C" void kernel_launch(void* const* d_in, const int* in_sizes, int n_in,
                              void* d_out, int out_size) {
    const float* x  = (const float*)d_in[0];
    const float* cb = (const float*)d_in[1];
    float* out = (float*)d_out;

    cudaFuncSetAttribute(filter_kernel,
                         cudaFuncAttributeMaxDynamicSharedMemorySize, SMEM_TOTAL);

    cnorm_kernel<<<KCODE / 256, 256>>>(cb);
    xnorm_kernel<<<64, 256>>>(x);
    filter_kernel<<<NPIX / 128, 256, SMEM_TOTAL>>>(x, cb);
    scan_kernel<<<NPIX / 8, 256>>>();
    rescore_kernel<<<NPIX / 256, 256>>>(x, cb);
    output_kernel<<<NPIX / 128, 256>>>(x, cb, out);
    finalize_kernel<<<1, 512>>>(out, out_size);
}

// round 6
// speedup vs baseline: 12.6553x; 12.5169x over previous
#include <cuda_runtime.h>
#include <cfloat>
#include <stdint.h>

// x [64,256,32,32] f32, codebook [1024,256] f32
#define D_DIM   256
#define HW_DIM  1024
#define NPIX    65536
#define KCODE   1024
#define TOT_ELEMS 16777216

typedef unsigned long long u64;

// Scratch (device globals; allocation-free)
__device__ float  g_cn[KCODE];
__device__ float  g_xn[NPIX];
__device__ double g_partial[512];

// ===================== packed f32x2 helpers (sm_100+) =====================
__device__ __forceinline__ u64 fma2(u64 a, u64 b, u64 c) {
    u64 d;
    asm("fma.rn.f32x2 %0, %1, %2, %3;" : "=l"(d) : "l"(a), "l"(b), "l"(c));
    return d;
}
__device__ __forceinline__ u64 pack2(float lo, float hi) {
    u64 d;
    asm("mov.b64 %0, {%1, %2};" : "=l"(d) : "f"(lo), "f"(hi));
    return d;
}
__device__ __forceinline__ float lo2(u64 v) {
    float l, h;
    asm("mov.b64 {%0, %1}, %2;" : "=f"(l), "=f"(h) : "l"(v));
    return l;
}
__device__ __forceinline__ float hi2(u64 v) {
    float l, h;
    asm("mov.b64 {%0, %1}, %2;" : "=f"(l), "=f"(h) : "l"(v));
    return h;
}
__device__ __forceinline__ u64 swap2(u64 v) {
    float l, h;
    asm("mov.b64 {%0, %1}, %2;" : "=f"(l), "=f"(h) : "l"(v));
    return pack2(h, l);
}

// ---------------------------------------------------------------------------
// norms (scalar-sequential order — bit-exact-validated in round 2)
// ---------------------------------------------------------------------------
__global__ void cnorm_kernel(const float* __restrict__ cb) {
    int k = blockIdx.x * 256 + threadIdx.x;
    const float* row = cb + (size_t)k * D_DIM;
    float s = 0.f;
    for (int d = 0; d < D_DIM; d++) s = __fadd_rn(s, __fmul_rn(row[d], row[d]));
    g_cn[k] = s;
}
__global__ void xnorm_kernel(const float* __restrict__ x) {
    int b = blockIdx.x, t = threadIdx.x;
    const float* xb = x + (size_t)b * D_DIM * HW_DIM + t * 4;
    float sa[4] = {0.f, 0.f, 0.f, 0.f};
    for (int d = 0; d < D_DIM; d++) {
        float4 v = *(const float4*)(xb + (size_t)d * HW_DIM);
        sa[0] = __fadd_rn(sa[0], __fmul_rn(v.x, v.x));
        sa[1] = __fadd_rn(sa[1], __fmul_rn(v.y, v.y));
        sa[2] = __fadd_rn(sa[2], __fmul_rn(v.z, v.z));
        sa[3] = __fadd_rn(sa[3], __fmul_rn(v.w, v.w));
    }
    int p = b * HW_DIM + t * 4;
#pragma unroll
    for (int j = 0; j < 4; j++) g_xn[p + j] = sa[j];
}

// ---------------------------------------------------------------------------
// Main VQ: 128x1024x256 fp32 GEMM via fma.rn.f32x2 (each lane is an exact
// single-accumulator, d-ascending fused-FMA chain — bit-identical to round 2),
// reference-rounded d2, lowest-index argmin, STE output, double loss partial.
// ---------------------------------------------------------------------------
__global__ __launch_bounds__(256, 2)
void vq_kernel(const float* __restrict__ x,
               const float* __restrict__ cb,
               float* __restrict__ out) {
    __shared__ float As[16][128];    // [dk][pixel]
    __shared__ float Bs[16][132];    // [dk][code] (+4 pad)
    __shared__ float cns[KCODE];
    __shared__ float xns[128];
    __shared__ float bestv[128];
    __shared__ int   besti[128];
    __shared__ double red[256];

    const int t  = threadIdx.x;
    const int tx = t & 15;
    const int ty = t >> 4;
    const int p0   = blockIdx.x * 128;
    const int bimg = p0 >> 10;
    const int hwb  = p0 & 1023;
    const float* xb = x + (size_t)bimg * D_DIM * HW_DIM + hwb;

#pragma unroll
    for (int i = 0; i < 4; i++) cns[t + i * 256] = g_cn[t + i * 256];
    if (t < 128) {
        xns[t] = g_xn[p0 + t];
        bestv[t] = FLT_MAX; besti[t] = 0x7fffffff;
    }
    __syncthreads();

    const int dkA0 = t >> 5;
    const int dkA1 = dkA0 + 8;
    const int ppA  = (t & 31) * 4;
    const int cc0  = t >> 2;
    const int cc1  = cc0 + 64;
    const int ds0  = (t & 3) * 4;

    for (int nc = 0; nc < 8; nc++) {
        const int cbase = nc * 128;

        // accN[i][jp]: {x_{2i}*c_{2jp}, x_{2i+1}*c_{2jp+1}} sums
        // accS[i][jp]: {x_{2i}*c_{2jp+1}, x_{2i+1}*c_{2jp}} sums
        u64 accN[4][4], accS[4][4];
#pragma unroll
        for (int i = 0; i < 4; i++)
#pragma unroll
            for (int j = 0; j < 4; j++) { accN[i][j] = 0ull; accS[i][j] = 0ull; }

        float4 ra0, ra1, rb0, rb1;
        {
            ra0 = *(const float4*)(xb + (size_t)dkA0 * HW_DIM + ppA);
            ra1 = *(const float4*)(xb + (size_t)dkA1 * HW_DIM + ppA);
            rb0 = *(const float4*)(cb + (size_t)(cbase + cc0) * D_DIM + ds0);
            rb1 = *(const float4*)(cb + (size_t)(cbase + cc1) * D_DIM + ds0);
        }

        for (int kc = 0; kc < 16; kc++) {
            __syncthreads();
            *(float4*)&As[dkA0][ppA] = ra0;
            *(float4*)&As[dkA1][ppA] = ra1;
            Bs[ds0 + 0][cc0] = rb0.x; Bs[ds0 + 1][cc0] = rb0.y;
            Bs[ds0 + 2][cc0] = rb0.z; Bs[ds0 + 3][cc0] = rb0.w;
            Bs[ds0 + 0][cc1] = rb1.x; Bs[ds0 + 1][cc1] = rb1.y;
            Bs[ds0 + 2][cc1] = rb1.z; Bs[ds0 + 3][cc1] = rb1.w;
            __syncthreads();

            if (kc < 15) {
                const int kn = kc + 1;
                ra0 = *(const float4*)(xb + (size_t)(kn * 16 + dkA0) * HW_DIM + ppA);
                ra1 = *(const float4*)(xb + (size_t)(kn * 16 + dkA1) * HW_DIM + ppA);
                rb0 = *(const float4*)(cb + (size_t)(cbase + cc0) * D_DIM + kn * 16 + ds0);
                rb1 = *(const float4*)(cb + (size_t)(cbase + cc1) * D_DIM + kn * 16 + ds0);
            }

#pragma unroll
            for (int dk = 0; dk < 16; dk++) {
                // a: 4 natural pixel pairs; b: 4 natural + 4 swapped code pairs
                const ulonglong2 aq0 = *(const ulonglong2*)&As[dk][ty * 8];
                const ulonglong2 aq1 = *(const ulonglong2*)&As[dk][ty * 8 + 4];
                const ulonglong2 bq0 = *(const ulonglong2*)&Bs[dk][tx * 8];
                const ulonglong2 bq1 = *(const ulonglong2*)&Bs[dk][tx * 8 + 4];
                u64 ap[4] = {aq0.x, aq0.y, aq1.x, aq1.y};
                u64 bn[4] = {bq0.x, bq0.y, bq1.x, bq1.y};
                u64 bs[4] = {swap2(bq0.x), swap2(bq0.y), swap2(bq1.x), swap2(bq1.y)};
#pragma unroll
                for (int i = 0; i < 4; i++)
#pragma unroll
                    for (int j = 0; j < 4; j++) {
                        accN[i][j] = fma2(ap[i], bn[j], accN[i][j]);
                        accS[i][j] = fma2(ap[i], bs[j], accS[i][j]);
                    }
            }
        }

        // Epilogue: d2 = fl(fl(xn - 2*dot) + cn); lowest-index ties on rounded
        // values. Ascending code order inside; shfl-reduce across tx group.
#pragma unroll
        for (int i = 0; i < 4; i++) {
#pragma unroll
            for (int e = 0; e < 2; e++) {
                const int r = ty * 8 + 2 * i + e;
                const float xn = xns[r];
                float bv = FLT_MAX;
                int   bi = 0x7fffffff;
#pragma unroll
                for (int jp = 0; jp < 4; jp++) {
                    float v0 = e ? hi2(accS[i][jp]) : lo2(accN[i][jp]);  // code 2jp
                    float v1 = e ? hi2(accN[i][jp]) : lo2(accS[i][jp]);  // code 2jp+1
                    const int c0 = cbase + tx * 8 + 2 * jp;
                    float d0 = __fadd_rn(__fadd_rn(xn, __fmul_rn(-2.f, v0)), cns[c0]);
                    float d1 = __fadd_rn(__fadd_rn(xn, __fmul_rn(-2.f, v1)), cns[c0 + 1]);
                    if (d0 < bv) { bv = d0; bi = c0; }
                    if (d1 < bv) { bv = d1; bi = c0 + 1; }
                }
#pragma unroll
                for (int off = 8; off > 0; off >>= 1) {
                    float ov = __shfl_down_sync(0xffffffffu, bv, off, 16);
                    int   oi = __shfl_down_sync(0xffffffffu, bi, off, 16);
                    if (ov < bv || (ov == bv && oi < bi)) { bv = ov; bi = oi; }
                }
                if (tx == 0) {
                    if (bv < bestv[r] || (bv == bestv[r] && bi < besti[r])) {
                        bestv[r] = bv; besti[r] = bi;
                    }
                }
            }
        }
    }
    __syncthreads();

    // Output: STE rounding fl(x + fl(q-x)); loss from fl(x-q)^2 in double.
    double lsum = 0.0;
#pragma unroll 4
    for (int m = 0; m < 128; m++) {
        int e  = m * 256 + t;
        int d  = e >> 7;
        int pp = e & 127;
        size_t addr = (size_t)(bimg * D_DIM + d) * HW_DIM + hwb + pp;
        float q  = cb[(size_t)besti[pp] * D_DIM + d];
        float xv = x[addr];
        out[addr] = __fadd_rn(xv, __fsub_rn(q, xv));
        float diff = __fsub_rn(xv, q);
        lsum += (double)__fmul_rn(diff, diff);
    }
    red[t] = lsum;
    __syncthreads();
    for (int s = 128; s > 0; s >>= 1) {
        if (t < s) red[t] += red[t + s];
        __syncthreads();
    }
    if (t == 0) g_partial[blockIdx.x] = red[0];
}

// ---------------------------------------------------------------------------
__global__ void finalize_kernel(float* __restrict__ out, int out_size) {
    __shared__ double red[512];
    int t = threadIdx.x;
    red[t] = g_partial[t];
    __syncthreads();
    for (int s = 256; s > 0; s >>= 1) {
        if (t < s) red[t] += red[t + s];
        __syncthreads();
    }
    if (t == 0) {
        float m = (float)(red[0] / (double)TOT_ELEMS);
        float loss = (float)(1.25 * (double)m);
        for (int i = TOT_ELEMS; i < out_size; i++) out[i] = loss;
    }
}

// ---------------------------------------------------------------------------
extern "C" void kernel_launch(void* const* d_in, const int* in_sizes, int n_in,
                              void* d_out, int out_size) {
    const float* x  = (const float*)d_in[0];
    const float* cb = (const float*)d_in[1];
    float* out = (float*)d_out;

    cnorm_kernel<<<KCODE / 256, 256>>>(cb);
    xnorm_kernel<<<64, 256>>>(x);
    vq_kernel<<<NPIX / 128, 256>>>(x, cb, out);
    finalize_kernel<<<1, 512>>>(out, out_size);
}